// round 1
// baseline (speedup 1.0000x reference)
#include <cuda_runtime.h>

// ALIF forward scan.
// x_seq: [T, n_flat] fp32.  State v, a: [n_flat].
// Per step: v = dv*v + x; th = th0 + beta*a; s = (v > th); v -= s*th; a = da*a + s.
// Output spikes [T, n_flat] fp32.
//
// Parallel over neurons (columns); sequential over T inside each thread.
// Unroll-by-8 with batched loads/stores for MLP.

#define UNROLL 8

__global__ __launch_bounds__(256)
void ALIF_24309514895931_kernel(const float* __restrict__ x,
                                const float* __restrict__ v0,
                                const float* __restrict__ a0,
                                const float* __restrict__ dv_p,
                                const float* __restrict__ da_p,
                                const float* __restrict__ th_p,
                                const float* __restrict__ beta_p,
                                float* __restrict__ out,
                                int n_flat, int T) {
    int i = blockIdx.x * blockDim.x + threadIdx.x;
    if (i >= n_flat) return;

    const float dv   = *dv_p;
    const float da   = *da_p;
    const float th0  = *th_p;
    const float beta = *beta_p;

    float v = v0[i];
    float a = a0[i];

    const float* xp = x + i;
    float* op = out + i;

    int t = 0;
    for (; t + UNROLL <= T; t += UNROLL) {
        float xs[UNROLL];
        #pragma unroll
        for (int k = 0; k < UNROLL; k++) {
            xs[k] = xp[(unsigned)(t + k) * (unsigned)n_flat];
        }
        float ss[UNROLL];
        #pragma unroll
        for (int k = 0; k < UNROLL; k++) {
            v = fmaf(dv, v, xs[k]);
            float th = fmaf(beta, a, th0);
            float s = (v > th) ? 1.0f : 0.0f;
            v = fmaf(-s, th, v);
            a = fmaf(da, a, s);
            ss[k] = s;
        }
        #pragma unroll
        for (int k = 0; k < UNROLL; k++) {
            op[(unsigned)(t + k) * (unsigned)n_flat] = ss[k];
        }
    }
    // Tail (T not multiple of UNROLL)
    for (; t < T; t++) {
        float xv = xp[(unsigned)t * (unsigned)n_flat];
        v = fmaf(dv, v, xv);
        float th = fmaf(beta, a, th0);
        float s = (v > th) ? 1.0f : 0.0f;
        v = fmaf(-s, th, v);
        a = fmaf(da, a, s);
        op[(unsigned)t * (unsigned)n_flat] = s;
    }
}

extern "C" void kernel_launch(void* const* d_in, const int* in_sizes, int n_in,
                              void* d_out, int out_size) {
    // metadata order: x_seq, v, a, decay_v, decay_a, threshold, beta, alpha
    const float* x     = (const float*)d_in[0];
    const float* v0    = (const float*)d_in[1];
    const float* a0    = (const float*)d_in[2];
    const float* dv_p  = (const float*)d_in[3];
    const float* da_p  = (const float*)d_in[4];
    const float* th_p  = (const float*)d_in[5];
    const float* beta_p= (const float*)d_in[6];
    // alpha (d_in[7]) only affects backward surrogate; unused in forward.

    int n_flat = in_sizes[1];              // size of v
    int T      = in_sizes[0] / n_flat;     // x_seq elements / n_flat

    float* out = (float*)d_out;

    int threads = 256;
    int blocks = (n_flat + threads - 1) / threads;
    ALIF_24309514895931_kernel<<<blocks, threads>>>(
        x, v0, a0, dv_p, da_p, th_p, beta_p, out, n_flat, T);
}

// round 2
// speedup vs baseline: 1.4502x; 1.4502x over previous
#include <cuda_runtime.h>

// ALIF forward scan, software-pipelined.
// x_seq: [T, n_flat] fp32; state v, a: [n_flat]; out spikes [T, n_flat] fp32.
// v = dv*v + x; th = th0 + beta*a; s = (v>th); v -= s*th; a = da*a + s.
//
// Thread-per-neuron, sequential T. Double-buffered prefetch of 16 timesteps
// keeps 16 LDGs per thread in flight while the serial recurrence computes
// the previous block. Streaming ld/st hints (touch-once 512MB stream).

#define U 16

__global__ __launch_bounds__(64)
void ALIF_24309514895931_kernel(const float* __restrict__ x,
                                const float* __restrict__ v0,
                                const float* __restrict__ a0,
                                const float* __restrict__ dv_p,
                                const float* __restrict__ da_p,
                                const float* __restrict__ th_p,
                                const float* __restrict__ beta_p,
                                float* __restrict__ out,
                                int n_flat, int T) {
    int i = blockIdx.x * 64 + threadIdx.x;
    if (i >= n_flat) return;

    const float dv   = *dv_p;
    const float da   = *da_p;
    const float th0  = *th_p;
    const float beta = *beta_p;

    float v = v0[i];
    float a = a0[i];

    const float* xp = x + i;
    float* op = out + i;
    const unsigned stride = (unsigned)n_flat;

    const int nb = T / U;

    float bufA[U], bufB[U];

#define LOADBLK(buf, b)                                                     \
    {                                                                       \
        unsigned base = (unsigned)(b) * U * stride;                         \
        _Pragma("unroll")                                                   \
        for (int k = 0; k < U; k++)                                         \
            (buf)[k] = __ldcs(xp + base + (unsigned)k * stride);            \
    }

#define COMPBLK(buf, b)                                                     \
    {                                                                       \
        unsigned base = (unsigned)(b) * U * stride;                         \
        _Pragma("unroll")                                                   \
        for (int k = 0; k < U; k++) {                                       \
            v = fmaf(dv, v, (buf)[k]);                                      \
            float th = fmaf(beta, a, th0);                                  \
            float s = (v > th) ? 1.0f : 0.0f;                               \
            v = fmaf(-s, th, v);                                            \
            a = fmaf(da, a, s);                                             \
            __stcs(op + base + (unsigned)k * stride, s);                    \
        }                                                                   \
    }

    if (nb > 0) LOADBLK(bufA, 0);

    int b = 0;
    for (; b + 2 <= nb; b += 2) {
        LOADBLK(bufB, b + 1);          // prefetch next block
        COMPBLK(bufA, b);              // compute current (loads in flight)
        if (b + 2 < nb) LOADBLK(bufA, b + 2);
        COMPBLK(bufB, b + 1);
    }
    if (b < nb) {                      // odd nb: last block already in bufA
        COMPBLK(bufA, b);
        b++;
    }

    // tail (T not multiple of U)
    for (int t = nb * U; t < T; t++) {
        float xv = __ldcs(xp + (unsigned)t * stride);
        v = fmaf(dv, v, xv);
        float th = fmaf(beta, a, th0);
        float s = (v > th) ? 1.0f : 0.0f;
        v = fmaf(-s, th, v);
        a = fmaf(da, a, s);
        __stcs(op + (unsigned)t * stride, s);
    }
#undef LOADBLK
#undef COMPBLK
}

extern "C" void kernel_launch(void* const* d_in, const int* in_sizes, int n_in,
                              void* d_out, int out_size) {
    // metadata order: x_seq, v, a, decay_v, decay_a, threshold, beta, alpha
    const float* x      = (const float*)d_in[0];
    const float* v0     = (const float*)d_in[1];
    const float* a0     = (const float*)d_in[2];
    const float* dv_p   = (const float*)d_in[3];
    const float* da_p   = (const float*)d_in[4];
    const float* th_p   = (const float*)d_in[5];
    const float* beta_p = (const float*)d_in[6];
    // alpha (d_in[7]) only affects backward surrogate; unused in forward.

    int n_flat = in_sizes[1];
    int T      = in_sizes[0] / n_flat;

    float* out = (float*)d_out;

    int threads = 64;
    int blocks = (n_flat + threads - 1) / threads;   // 1024 for n_flat=65536
    ALIF_24309514895931_kernel<<<blocks, threads>>>(
        x, v0, a0, dv_p, da_p, th_p, beta_p, out, n_flat, T);
}